// round 1
// baseline (speedup 1.0000x reference)
#include <cuda_runtime.h>
#include <cstdint>

#define D        128
#define WARPS    8
#define RPW      16                 // rows per warp
#define TILE_ROWS (WARPS * RPW)     // 128 rows per CTA-tile
#define NTHREADS 256

// packed fp32x2 FMA (sm_100+)
__device__ __forceinline__ unsigned long long fma2(unsigned long long a,
                                                   unsigned long long b,
                                                   unsigned long long c) {
    unsigned long long d;
    asm("fma.rn.f32x2 %0, %1, %2, %3;" : "=l"(d) : "l"(a), "l"(b), "l"(c));
    return d;
}
__device__ __forceinline__ unsigned long long pack2(float lo, float hi) {
    unsigned long long d;
    asm("mov.b64 %0, {%1, %2};" : "=l"(d) : "f"(lo), "f"(hi));
    return d;
}
__device__ __forceinline__ void unpack2(unsigned long long a, float& lo, float& hi) {
    asm("mov.b64 {%0, %1}, %2;" : "=f"(lo), "=f"(hi) : "l"(a));
}

extern "C" __global__ void __launch_bounds__(NTHREADS, 1)
hh_kernel(const float* __restrict__ z, const float* __restrict__ v,
          const float* __restrict__ W, const float* __restrict__ b,
          float* __restrict__ out, int B)
{
    extern __shared__ float smem[];
    float* Wt   = smem;               // [128][128]  W transposed: Wt[k][j] = W[j][k]
    float* vdup = smem + D * D;       // [WARPS*RPW][128] duplicated pairs: (v,v) per k

    const int tid  = threadIdx.x;
    const int warp = tid >> 5;
    const int lane = tid & 31;

    // ---- one-time: transpose W into shared (conflict-free STS; strided LDG hits L2) ----
    for (int idx = tid; idx < D * D; idx += NTHREADS) {
        int k = idx >> 7;        // row of Wt
        int j = idx & 127;       // col of Wt (consecutive tid -> consecutive j: no STS conflicts)
        Wt[k * D + j] = W[j * D + k];
    }

    // bias for this lane's 4 outputs, packed
    float4 bb = *(const float4*)&b[lane * 4];
    const unsigned long long b01 = pack2(bb.x, bb.y);
    const unsigned long long b23 = pack2(bb.z, bb.w);
    __syncthreads();

    const int ntiles = B / TILE_ROWS;
    float* vd = vdup + (warp * RPW) * (D * 2);   // this warp's private dup buffer

    for (int tile = blockIdx.x; tile < ntiles; tile += gridDim.x) {
        const int row0 = tile * TILE_ROWS + warp * RPW;

        // ---- stage v rows: coalesced float4 LDG (MLP=16), then duplicated STS ----
        float4 vreg[RPW];
        #pragma unroll
        for (int r = 0; r < RPW; r++)
            vreg[r] = *(const float4*)&v[(row0 + r) * D + lane * 4];
        #pragma unroll
        for (int r = 0; r < RPW; r++) {
            float* dst = vd + r * (D * 2) + lane * 8;   // 32B-aligned per lane
            *(float4*)(dst)     = make_float4(vreg[r].x, vreg[r].x, vreg[r].y, vreg[r].y);
            *(float4*)(dst + 4) = make_float4(vreg[r].z, vreg[r].z, vreg[r].w, vreg[r].w);
        }
        __syncwarp();

        // ---- accumulators: v_new[j0..j0+3] for RPW rows, as f32x2 pairs ----
        unsigned long long acc0[RPW], acc1[RPW];
        #pragma unroll
        for (int r = 0; r < RPW; r++) { acc0[r] = b01; acc1[r] = b23; }

        // ---- main GEMV loop: 2 k per iteration ----
        const float* wbase = Wt + lane * 4;
        #pragma unroll 2
        for (int k2 = 0; k2 < D / 2; k2++) {
            const float* wp = wbase + (2 * k2) * D;
            ulonglong2 w0 = *(const ulonglong2*)(wp);        // (W[k][j0],W[k][j1]) , (W[k][j2],W[k][j3])
            ulonglong2 w1 = *(const ulonglong2*)(wp + D);    // same for k+1
            #pragma unroll
            for (int r = 0; r < RPW; r++) {
                // broadcast 16B: ((v[k],v[k]),(v[k+1],v[k+1]))  -> 1 smem wavefront
                ulonglong2 vv = *(const ulonglong2*)(vd + r * (D * 2) + k2 * 4);
                acc0[r] = fma2(vv.x, w0.x, acc0[r]);
                acc1[r] = fma2(vv.x, w0.y, acc1[r]);
                acc0[r] = fma2(vv.y, w1.x, acc0[r]);
                acc1[r] = fma2(vv.y, w1.y, acc1[r]);
            }
        }

        // ---- epilogue: per-row Householder reflection ----
        #pragma unroll
        for (int r = 0; r < RPW; r++) {
            const int off = (row0 + r) * D + lane * 4;
            float4 z4 = *(const float4*)&z[off];
            float a0x, a0y, a1x, a1y;
            unpack2(acc0[r], a0x, a0y);
            unpack2(acc1[r], a1x, a1y);

            float dot = a0x * z4.x + a0y * z4.y + a1x * z4.z + a1y * z4.w;
            float nrm = a0x * a0x + a0y * a0y + a1x * a1x + a1y * a1y;
            #pragma unroll
            for (int s = 16; s; s >>= 1) {
                dot += __shfl_xor_sync(0xffffffffu, dot, s);
                nrm += __shfl_xor_sync(0xffffffffu, nrm, s);
            }
            float sc = 2.0f * dot / nrm;

            float4 o;
            o.x = z4.x - sc * a0x;
            o.y = z4.y - sc * a0y;
            o.z = z4.z - sc * a1x;
            o.w = z4.w - sc * a1y;
            *(float4*)&out[off] = o;
        }
        __syncwarp();   // vdup reuse safety before next tile overwrite
    }
}

extern "C" void kernel_launch(void* const* d_in, const int* in_sizes, int n_in,
                              void* d_out, int out_size) {
    const float* z = (const float*)d_in[0];
    const float* v = (const float*)d_in[1];
    const float* W = (const float*)d_in[2];
    const float* b = (const float*)d_in[3];
    float* out = (float*)d_out;

    const int B = in_sizes[0] / D;                       // 524288
    const size_t smem = (size_t)D * D * 4                // Wt: 64 KB
                      + (size_t)WARPS * RPW * D * 2 * 4; // vdup: 128 KB  -> 192 KB total

    cudaFuncSetAttribute(hh_kernel, cudaFuncAttributeMaxDynamicSharedMemorySize, (int)smem);
    hh_kernel<<<148, NTHREADS, smem>>>(z, v, W, b, out, B);
}

// round 4
// speedup vs baseline: 2.1596x; 2.1596x over previous
#include <cuda_runtime.h>
#include <cuda_bf16.h>
#include <cstdint>

#define DDIM   128
#define TILE_M 128
#define NTH    256
#define NWARP  8

#define A_STRIDE 272                         // bytes per A row (256 data + 16 pad)
#define A_HI_OFF 0
#define A_LO_OFF (TILE_M * A_STRIDE)         // 34816
#define PDOT_OFF (2 * TILE_M * A_STRIDE)     // 69632
#define PNRM_OFF (PDOT_OFF + NWARP * TILE_M * 4)
#define SC_OFF   (PNRM_OFF + NWARP * TILE_M * 4)
#define SMEM_TOTAL (SC_OFF + TILE_M * 4)     // 78336 B

__device__ __forceinline__ uint32_t s2u(const void* p) {
    return (uint32_t)__cvta_generic_to_shared(p);
}

__device__ __forceinline__ void mma_bf16(float& d0, float& d1, float& d2, float& d3,
                                         uint32_t a0, uint32_t a1, uint32_t a2, uint32_t a3,
                                         uint32_t b0, uint32_t b1) {
    asm volatile("mma.sync.aligned.m16n8k16.row.col.f32.bf16.bf16.f32 "
                 "{%0,%1,%2,%3}, {%4,%5,%6,%7}, {%8,%9}, {%0,%1,%2,%3};"
                 : "+f"(d0), "+f"(d1), "+f"(d2), "+f"(d3)
                 : "r"(a0), "r"(a1), "r"(a2), "r"(a3), "r"(b0), "r"(b1));
}
__device__ __forceinline__ void ldmx4(uint32_t& r0, uint32_t& r1, uint32_t& r2, uint32_t& r3,
                                      uint32_t addr) {
    asm volatile("ldmatrix.sync.aligned.m8n8.x4.shared.b16 {%0,%1,%2,%3}, [%4];"
                 : "=r"(r0), "=r"(r1), "=r"(r2), "=r"(r3) : "r"(addr));
}
// split fp32 pair -> packed bf16x2 hi and lo (lo = residual)
__device__ __forceinline__ void split2(float2 x, uint32_t& h, uint32_t& l) {
    __nv_bfloat16 h0 = __float2bfloat16_rn(x.x);
    __nv_bfloat16 h1 = __float2bfloat16_rn(x.y);
    __nv_bfloat16 l0 = __float2bfloat16_rn(x.x - __bfloat162float(h0));
    __nv_bfloat16 l1 = __float2bfloat16_rn(x.y - __bfloat162float(h1));
    __nv_bfloat162 hh = __halves2bfloat162(h0, h1);
    __nv_bfloat162 ll = __halves2bfloat162(l0, l1);
    h = *(uint32_t*)&hh;
    l = *(uint32_t*)&ll;
}

extern "C" __global__ void __launch_bounds__(NTH, 1)
hh_hmma_kernel(const float* __restrict__ z, const float* __restrict__ v,
               const float* __restrict__ W, const float* __restrict__ b,
               float* __restrict__ out, int B)
{
    extern __shared__ char sm[];
    float* psd = (float*)(sm + PDOT_OFF);
    float* psn = (float*)(sm + PNRM_OFF);
    float* scs = (float*)(sm + SC_OFF);

    const int tid  = threadIdx.x;
    const int w    = tid >> 5;
    const int lane = tid & 31;
    const int n0   = w * 16;                    // this warp's 16 output columns
    const int qk   = (lane & 3) * 2;            // k-pair / col-pair offset within frag
    const int qr   = lane >> 2;                 // frag row 0..7

    const uint32_t sm_u = s2u(sm);
    // per-lane ldmatrix base (row = lane%16, 16B chunk = lane/16)
    const uint32_t ahib = sm_u + A_HI_OFF + (uint32_t)(lane & 15) * A_STRIDE + (uint32_t)(lane >> 4) * 16;
    const uint32_t alob = ahib + (A_LO_OFF - A_HI_OFF);

    // ---- one-time: resident B fragments (W hi/lo) + bias pairs ----
    // B[k][n] = W[n][k];  frag b0 = {B[k0][n],B[k0+1][n]}, b1 = {B[k0+8][n],B[k0+9][n]}
    uint32_t bh[2][8][2], bl[2][8][2];
    #pragma unroll
    for (int nt = 0; nt < 2; nt++) {
        const int n = n0 + nt * 8 + qr;
        #pragma unroll
        for (int kk = 0; kk < 8; kk++) {
            float2 x0 = *(const float2*)&W[n * DDIM + kk * 16 + qk];
            float2 x1 = *(const float2*)&W[n * DDIM + kk * 16 + qk + 8];
            split2(x0, bh[nt][kk][0], bl[nt][kk][0]);
            split2(x1, bh[nt][kk][1], bl[nt][kk][1]);
        }
    }
    float2 bias0 = *(const float2*)&b[n0 + qk];       // cols for nt=0
    float2 bias1 = *(const float2*)&b[n0 + 8 + qk];   // cols for nt=1

    const int ntiles = B / TILE_M;

    for (int tile = blockIdx.x; tile < ntiles; tile += gridDim.x) {
        const size_t tb = (size_t)tile * TILE_M * DDIM;

        // ---- stage: v tile -> bf16 hi/lo smem (padded rows) ----
        #pragma unroll
        for (int it = 0; it < 32; it++) {
            int p   = tid + it * NTH;          // pair index 0..8191
            int row = p >> 6;
            int kp  = p & 63;
            float2 x = *(const float2*)&v[tb + row * DDIM + kp * 2];
            uint32_t h, l;
            split2(x, h, l);
            *(uint32_t*)(sm + A_HI_OFF + row * A_STRIDE + kp * 4) = h;
            *(uint32_t*)(sm + A_LO_OFF + row * A_STRIDE + kp * 4) = l;
        }
        __syncthreads();

        // ---- MMA + per-m-tile partial dot/norm ----
        float acc[8][2][4];
        #pragma unroll
        for (int mt = 0; mt < 8; mt++)
            #pragma unroll
            for (int nt = 0; nt < 2; nt++)
                #pragma unroll
                for (int i = 0; i < 4; i++) acc[mt][nt][i] = 0.f;

        #pragma unroll
        for (int mt = 0; mt < 8; mt++) {
            #pragma unroll
            for (int kk = 0; kk < 8; kk++) {
                uint32_t ah0, ah1, ah2, ah3, al0, al1, al2, al3;
                const uint32_t off = (uint32_t)mt * (16 * A_STRIDE) + (uint32_t)kk * 32;
                ldmx4(ah0, ah1, ah2, ah3, ahib + off);
                ldmx4(al0, al1, al2, al3, alob + off);
                #pragma unroll
                for (int nt = 0; nt < 2; nt++) {
                    mma_bf16(acc[mt][nt][0], acc[mt][nt][1], acc[mt][nt][2], acc[mt][nt][3],
                             ah0, ah1, ah2, ah3, bh[nt][kk][0], bh[nt][kk][1]);
                    mma_bf16(acc[mt][nt][0], acc[mt][nt][1], acc[mt][nt][2], acc[mt][nt][3],
                             ah0, ah1, ah2, ah3, bl[nt][kk][0], bl[nt][kk][1]);
                    mma_bf16(acc[mt][nt][0], acc[mt][nt][1], acc[mt][nt][2], acc[mt][nt][3],
                             al0, al1, al2, al3, bh[nt][kk][0], bh[nt][kk][1]);
                }
            }
            // epilogue part 1: partial dot & norm for the 2 rows this lane owns
            {
                const int rt = mt * 16 + qr;                   // row in tile (and rt+8)
                const float* zr0 = z + tb + (size_t)rt * DDIM + n0;
                const float* zr1 = zr0 + 8 * DDIM;
                float2 za = *(const float2*)&zr0[qk];
                float2 zb = *(const float2*)&zr0[qk + 8];
                float2 zc = *(const float2*)&zr1[qk];
                float2 zd = *(const float2*)&zr1[qk + 8];

                float vn00 = acc[mt][0][0] + bias0.x, vn01 = acc[mt][0][1] + bias0.y;
                float vn10 = acc[mt][1][0] + bias1.x, vn11 = acc[mt][1][1] + bias1.y;
                float vn20 = acc[mt][0][2] + bias0.x, vn21 = acc[mt][0][3] + bias0.y;
                float vn30 = acc[mt][1][2] + bias1.x, vn31 = acc[mt][1][3] + bias1.y;

                float d0 = vn00 * za.x + vn01 * za.y + vn10 * zb.x + vn11 * zb.y;
                float m0 = vn00 * vn00 + vn01 * vn01 + vn10 * vn10 + vn11 * vn11;
                float d1 = vn20 * zc.x + vn21 * zc.y + vn30 * zd.x + vn31 * zd.y;
                float m1 = vn20 * vn20 + vn21 * vn21 + vn30 * vn30 + vn31 * vn31;

                d0 += __shfl_xor_sync(0xffffffffu, d0, 1);
                d0 += __shfl_xor_sync(0xffffffffu, d0, 2);
                m0 += __shfl_xor_sync(0xffffffffu, m0, 1);
                m0 += __shfl_xor_sync(0xffffffffu, m0, 2);
                d1 += __shfl_xor_sync(0xffffffffu, d1, 1);
                d1 += __shfl_xor_sync(0xffffffffu, d1, 2);
                m1 += __shfl_xor_sync(0xffffffffu, m1, 1);
                m1 += __shfl_xor_sync(0xffffffffu, m1, 2);

                if ((lane & 3) == 0) {
                    psd[w * TILE_M + rt]     = d0;
                    psd[w * TILE_M + rt + 8] = d1;
                    psn[w * TILE_M + rt]     = m0;
                    psn[w * TILE_M + rt + 8] = m1;
                }
            }
        }
        __syncthreads();

        // ---- cross-warp reduce -> scale per row ----
        if (tid < TILE_M) {
            float dt = 0.f, nm = 0.f;
            #pragma unroll
            for (int ww = 0; ww < NWARP; ww++) {
                dt += psd[ww * TILE_M + tid];
                nm += psn[ww * TILE_M + tid];
            }
            scs[tid] = 2.0f * dt / nm;
        }
        __syncthreads();

        // ---- reflect + store ----
        #pragma unroll
        for (int mt = 0; mt < 8; mt++) {
            const int rt = mt * 16 + qr;
            const float s0 = scs[rt];
            const float s1 = scs[rt + 8];
            const float* zr0 = z + tb + (size_t)rt * DDIM + n0;
            const float* zr1 = zr0 + 8 * DDIM;
            float* or0 = out + tb + (size_t)rt * DDIM + n0;
            float* or1 = or0 + 8 * DDIM;

            float2 za = *(const float2*)&zr0[qk];
            float2 zb = *(const float2*)&zr0[qk + 8];
            float2 zc = *(const float2*)&zr1[qk];
            float2 zd = *(const float2*)&zr1[qk + 8];

            float vn00 = acc[mt][0][0] + bias0.x, vn01 = acc[mt][0][1] + bias0.y;
            float vn10 = acc[mt][1][0] + bias1.x, vn11 = acc[mt][1][1] + bias1.y;
            float vn20 = acc[mt][0][2] + bias0.x, vn21 = acc[mt][0][3] + bias0.y;
            float vn30 = acc[mt][1][2] + bias1.x, vn31 = acc[mt][1][3] + bias1.y;

            float2 o;
            o.x = za.x - s0 * vn00; o.y = za.y - s0 * vn01; *(float2*)&or0[qk]     = o;
            o.x = zb.x - s0 * vn10; o.y = zb.y - s0 * vn11; *(float2*)&or0[qk + 8] = o;
            o.x = zc.x - s1 * vn20; o.y = zc.y - s1 * vn21; *(float2*)&or1[qk]     = o;
            o.x = zd.x - s1 * vn30; o.y = zd.y - s1 * vn31; *(float2*)&or1[qk + 8] = o;
        }
        __syncthreads();   // protect A smem / psd before next iteration's writers
    }
}

extern "C" void kernel_launch(void* const* d_in, const int* in_sizes, int n_in,
                              void* d_out, int out_size) {
    const float* z = (const float*)d_in[0];
    const float* v = (const float*)d_in[1];
    const float* W = (const float*)d_in[2];
    const float* b = (const float*)d_in[3];
    float* out = (float*)d_out;

    const int B = in_sizes[0] / DDIM;

    cudaFuncSetAttribute(hh_hmma_kernel, cudaFuncAttributeMaxDynamicSharedMemorySize, SMEM_TOTAL);
    hh_hmma_kernel<<<148, NTH, SMEM_TOTAL>>>(z, v, W, b, out, B);
}

// round 5
// speedup vs baseline: 2.9555x; 1.3685x over previous
#include <cuda_runtime.h>
#include <cuda_bf16.h>
#include <cstdint>

#define DDIM   128
#define TILE_M 128
#define NTH    256
#define NWARP  8

// ---- smem layout (bytes) ----
#define VRAW_OFF 0                           // raw v tile, 128 rows x 512B
#define VRAW_SZ  (TILE_M * DDIM * 4)         // 65536
#define A_STRIDE 272                         // bf16 A row: 256 data + 16 pad
#define A_HI_OFF (VRAW_OFF + VRAW_SZ)        // 65536
#define A_LO_OFF (A_HI_OFF + TILE_M * A_STRIDE)
#define ZS_OFF   (A_LO_OFF + TILE_M * A_STRIDE)   // 135168
#define ZS_FSTRIDE 136                       // floats per padded z row (544B)
#define ZS_SZ    (TILE_M * ZS_FSTRIDE * 4)   // 69632
#define PDOT_OFF (ZS_OFF + ZS_SZ)            // 204800
#define PNRM_OFF (PDOT_OFF + NWARP * TILE_M * 4)
#define SC_OFF   (PNRM_OFF + NWARP * TILE_M * 4)
#define SMEM_TOTAL (SC_OFF + TILE_M * 4)     // 213504

__device__ __forceinline__ uint32_t s2u(const void* p) {
    return (uint32_t)__cvta_generic_to_shared(p);
}
__device__ __forceinline__ void cpa16(uint32_t dst, const void* src) {
    asm volatile("cp.async.cg.shared.global [%0], [%1], 16;" :: "r"(dst), "l"(src) : "memory");
}
__device__ __forceinline__ void cpa_commit() {
    asm volatile("cp.async.commit_group;" ::: "memory");
}
__device__ __forceinline__ void cpa_wait1() {
    asm volatile("cp.async.wait_group 1;" ::: "memory");
}
__device__ __forceinline__ void mma_bf16(float& d0, float& d1, float& d2, float& d3,
                                         uint32_t a0, uint32_t a1, uint32_t a2, uint32_t a3,
                                         uint32_t b0, uint32_t b1) {
    asm volatile("mma.sync.aligned.m16n8k16.row.col.f32.bf16.bf16.f32 "
                 "{%0,%1,%2,%3}, {%4,%5,%6,%7}, {%8,%9}, {%0,%1,%2,%3};"
                 : "+f"(d0), "+f"(d1), "+f"(d2), "+f"(d3)
                 : "r"(a0), "r"(a1), "r"(a2), "r"(a3), "r"(b0), "r"(b1));
}
__device__ __forceinline__ void ldmx4(uint32_t& r0, uint32_t& r1, uint32_t& r2, uint32_t& r3,
                                      uint32_t addr) {
    asm volatile("ldmatrix.sync.aligned.m8n8.x4.shared.b16 {%0,%1,%2,%3}, [%4];"
                 : "=r"(r0), "=r"(r1), "=r"(r2), "=r"(r3) : "r"(addr));
}
__device__ __forceinline__ void split2(float2 x, uint32_t& h, uint32_t& l) {
    __nv_bfloat16 h0 = __float2bfloat16_rn(x.x);
    __nv_bfloat16 h1 = __float2bfloat16_rn(x.y);
    __nv_bfloat16 l0 = __float2bfloat16_rn(x.x - __bfloat162float(h0));
    __nv_bfloat16 l1 = __float2bfloat16_rn(x.y - __bfloat162float(h1));
    __nv_bfloat162 hh = __halves2bfloat162(h0, h1);
    __nv_bfloat162 ll = __halves2bfloat162(l0, l1);
    h = *(uint32_t*)&hh;
    l = *(uint32_t*)&ll;
}

extern "C" __global__ void __launch_bounds__(NTH, 1)
hh_hmma_kernel(const float* __restrict__ z, const float* __restrict__ v,
               const float* __restrict__ W, const float* __restrict__ b,
               float* __restrict__ out, int B)
{
    extern __shared__ char sm[];
    float* vraw = (float*)(sm + VRAW_OFF);
    float* zs   = (float*)(sm + ZS_OFF);
    float* psd  = (float*)(sm + PDOT_OFF);
    float* psn  = (float*)(sm + PNRM_OFF);
    float* scs  = (float*)(sm + SC_OFF);

    const int tid  = threadIdx.x;
    const int w    = tid >> 5;
    const int lane = tid & 31;
    const int n0   = w * 16;
    const int qk   = (lane & 3) * 2;
    const int qr   = lane >> 2;

    const uint32_t sm_u   = s2u(sm);
    const uint32_t vraw_u = sm_u + VRAW_OFF;
    const uint32_t zs_u   = sm_u + ZS_OFF;
    const uint32_t ahib   = sm_u + A_HI_OFF + (uint32_t)(lane & 15) * A_STRIDE + (uint32_t)(lane >> 4) * 16;
    const uint32_t alob   = ahib + (uint32_t)(A_LO_OFF - A_HI_OFF);

    // ---- one-time: resident B fragments (W hi/lo split) + bias ----
    uint32_t bh[2][8][2], bl[2][8][2];
    #pragma unroll
    for (int nt = 0; nt < 2; nt++) {
        const int n = n0 + nt * 8 + qr;
        #pragma unroll
        for (int kk = 0; kk < 8; kk++) {
            float2 x0 = *(const float2*)&W[n * DDIM + kk * 16 + qk];
            float2 x1 = *(const float2*)&W[n * DDIM + kk * 16 + qk + 8];
            split2(x0, bh[nt][kk][0], bl[nt][kk][0]);
            split2(x1, bh[nt][kk][1], bl[nt][kk][1]);
        }
    }
    float2 bias0 = *(const float2*)&b[n0 + qk];
    float2 bias1 = *(const float2*)&b[n0 + 8 + qk];

    const int ntiles = B / TILE_M;

    // ---- prologue: prefetch v for first tile (group V) ----
    {
        int t0 = blockIdx.x;
        if (t0 < ntiles) {
            const float* src = v + (size_t)t0 * TILE_M * DDIM;
            #pragma unroll
            for (int j = 0; j < 16; j++) {
                int c = tid + j * NTH;                         // 16B chunk id
                cpa16(vraw_u + (uint32_t)c * 16, src + (size_t)c * 4);
            }
        }
        cpa_commit();
    }

    for (int tile = blockIdx.x; tile < ntiles; tile += gridDim.x) {
        const size_t tb = (size_t)tile * TILE_M * DDIM;

        // ---- issue z prefetch for THIS tile (group Z); consumed after MMA ----
        {
            const float* src = z + tb;
            #pragma unroll
            for (int j = 0; j < 16; j++) {
                int c  = tid + j * NTH;
                int r4 = c >> 5, c4 = c & 31;
                cpa16(zs_u + (uint32_t)(r4 * (ZS_FSTRIDE * 4) + c4 * 16), src + (size_t)c * 4);
            }
            cpa_commit();
        }

        // ---- wait v prefetch (group V from previous iteration / prologue) ----
        cpa_wait1();            // newest (Z) may still fly; V complete
        __syncthreads();

        // ---- convert v_raw (smem) -> bf16 hi/lo A tiles ----
        #pragma unroll
        for (int it = 0; it < 32; it++) {
            int p   = tid + it * NTH;
            int row = p >> 6;
            int kp  = p & 63;
            float2 x = *(const float2*)&vraw[row * DDIM + kp * 2];
            uint32_t h, l;
            split2(x, h, l);
            *(uint32_t*)(sm + A_HI_OFF + row * A_STRIDE + kp * 4) = h;
            *(uint32_t*)(sm + A_LO_OFF + row * A_STRIDE + kp * 4) = l;
        }
        __syncthreads();

        // ---- issue v prefetch for NEXT tile (group V) ----
        {
            int nxt = tile + gridDim.x;
            if (nxt < ntiles) {
                const float* src = v + (size_t)nxt * TILE_M * DDIM;
                #pragma unroll
                for (int j = 0; j < 16; j++) {
                    int c = tid + j * NTH;
                    cpa16(vraw_u + (uint32_t)c * 16, src + (size_t)c * 4);
                }
            }
            cpa_commit();
        }

        // ---- MMA: 3-pass split bf16 ----
        float acc[8][2][4];
        #pragma unroll
        for (int mt = 0; mt < 8; mt++)
            #pragma unroll
            for (int nt = 0; nt < 2; nt++)
                #pragma unroll
                for (int i = 0; i < 4; i++) acc[mt][nt][i] = 0.f;

        #pragma unroll
        for (int mt = 0; mt < 8; mt++) {
            #pragma unroll
            for (int kk = 0; kk < 8; kk++) {
                uint32_t ah0, ah1, ah2, ah3, al0, al1, al2, al3;
                const uint32_t off = (uint32_t)mt * (16 * A_STRIDE) + (uint32_t)kk * 32;
                ldmx4(ah0, ah1, ah2, ah3, ahib + off);
                ldmx4(al0, al1, al2, al3, alob + off);
                #pragma unroll
                for (int nt = 0; nt < 2; nt++) {
                    mma_bf16(acc[mt][nt][0], acc[mt][nt][1], acc[mt][nt][2], acc[mt][nt][3],
                             ah0, ah1, ah2, ah3, bh[nt][kk][0], bh[nt][kk][1]);
                    mma_bf16(acc[mt][nt][0], acc[mt][nt][1], acc[mt][nt][2], acc[mt][nt][3],
                             ah0, ah1, ah2, ah3, bl[nt][kk][0], bl[nt][kk][1]);
                    mma_bf16(acc[mt][nt][0], acc[mt][nt][1], acc[mt][nt][2], acc[mt][nt][3],
                             al0, al1, al2, al3, bh[nt][kk][0], bh[nt][kk][1]);
                }
            }
        }

        // ---- wait z prefetch (group Z); V-next may still be in flight ----
        cpa_wait1();
        __syncthreads();

        // ---- partial dot/norm per row (z from smem) ----
        #pragma unroll
        for (int mt = 0; mt < 8; mt++) {
            const int rt = mt * 16 + qr;
            const float* zr0 = &zs[rt * ZS_FSTRIDE + n0];
            const float* zr1 = &zs[(rt + 8) * ZS_FSTRIDE + n0];
            float2 za = *(const float2*)&zr0[qk];
            float2 zb = *(const float2*)&zr0[qk + 8];
            float2 zc = *(const float2*)&zr1[qk];
            float2 zd = *(const float2*)&zr1[qk + 8];

            float vn00 = acc[mt][0][0] + bias0.x, vn01 = acc[mt][0][1] + bias0.y;
            float vn10 = acc[mt][1][0] + bias1.x, vn11 = acc[mt][1][1] + bias1.y;
            float vn20 = acc[mt][0][2] + bias0.x, vn21 = acc[mt][0][3] + bias0.y;
            float vn30 = acc[mt][1][2] + bias1.x, vn31 = acc[mt][1][3] + bias1.y;

            float d0 = vn00 * za.x + vn01 * za.y + vn10 * zb.x + vn11 * zb.y;
            float m0 = vn00 * vn00 + vn01 * vn01 + vn10 * vn10 + vn11 * vn11;
            float d1 = vn20 * zc.x + vn21 * zc.y + vn30 * zd.x + vn31 * zd.y;
            float m1 = vn20 * vn20 + vn21 * vn21 + vn30 * vn30 + vn31 * vn31;

            d0 += __shfl_xor_sync(0xffffffffu, d0, 1);
            d0 += __shfl_xor_sync(0xffffffffu, d0, 2);
            m0 += __shfl_xor_sync(0xffffffffu, m0, 1);
            m0 += __shfl_xor_sync(0xffffffffu, m0, 2);
            d1 += __shfl_xor_sync(0xffffffffu, d1, 1);
            d1 += __shfl_xor_sync(0xffffffffu, d1, 2);
            m1 += __shfl_xor_sync(0xffffffffu, m1, 1);
            m1 += __shfl_xor_sync(0xffffffffu, m1, 2);

            if ((lane & 3) == 0) {
                psd[w * TILE_M + rt]     = d0;
                psd[w * TILE_M + rt + 8] = d1;
                psn[w * TILE_M + rt]     = m0;
                psn[w * TILE_M + rt + 8] = m1;
            }
        }
        __syncthreads();

        // ---- cross-warp reduce -> per-row scale ----
        if (tid < TILE_M) {
            float dt = 0.f, nm = 0.f;
            #pragma unroll
            for (int ww = 0; ww < NWARP; ww++) {
                dt += psd[ww * TILE_M + tid];
                nm += psn[ww * TILE_M + tid];
            }
            scs[tid] = 2.0f * dt / nm;
        }
        __syncthreads();

        // ---- reflect + store ----
        #pragma unroll
        for (int mt = 0; mt < 8; mt++) {
            const int rt = mt * 16 + qr;
            const float s0 = scs[rt];
            const float s1 = scs[rt + 8];
            const float* zr0 = &zs[rt * ZS_FSTRIDE + n0];
            const float* zr1 = &zs[(rt + 8) * ZS_FSTRIDE + n0];
            float* or0 = out + tb + (size_t)rt * DDIM + n0;
            float* or1 = or0 + 8 * DDIM;

            float2 za = *(const float2*)&zr0[qk];
            float2 zb = *(const float2*)&zr0[qk + 8];
            float2 zc = *(const float2*)&zr1[qk];
            float2 zd = *(const float2*)&zr1[qk + 8];

            float vn00 = acc[mt][0][0] + bias0.x, vn01 = acc[mt][0][1] + bias0.y;
            float vn10 = acc[mt][1][0] + bias1.x, vn11 = acc[mt][1][1] + bias1.y;
            float vn20 = acc[mt][0][2] + bias0.x, vn21 = acc[mt][0][3] + bias0.y;
            float vn30 = acc[mt][1][2] + bias1.x, vn31 = acc[mt][1][3] + bias1.y;

            float2 o;
            o.x = za.x - s0 * vn00; o.y = za.y - s0 * vn01; *(float2*)&or0[qk]     = o;
            o.x = zb.x - s0 * vn10; o.y = zb.y - s0 * vn11; *(float2*)&or0[qk + 8] = o;
            o.x = zc.x - s1 * vn20; o.y = zc.y - s1 * vn21; *(float2*)&or1[qk]     = o;
            o.x = zd.x - s1 * vn30; o.y = zd.y - s1 * vn31; *(float2*)&or1[qk + 8] = o;
        }
        __syncthreads();   // protect zs / A / psd before next tile's writers
    }
}

extern "C" void kernel_launch(void* const* d_in, const int* in_sizes, int n_in,
                              void* d_out, int out_size) {
    const float* z = (const float*)d_in[0];
    const float* v = (const float*)d_in[1];
    const float* W = (const float*)d_in[2];
    const float* b = (const float*)d_in[3];
    float* out = (float*)d_out;

    const int B = in_sizes[0] / DDIM;

    cudaFuncSetAttribute(hh_hmma_kernel, cudaFuncAttributeMaxDynamicSharedMemorySize, SMEM_TOTAL);
    hh_hmma_kernel<<<148, NTH, SMEM_TOTAL>>>(z, v, W, b, out, B);
}